// round 5
// baseline (speedup 1.0000x reference)
#include <cuda_runtime.h>
#include <math.h>

#define KLEN   4096
#define NFREQ  2049      // K/2 + 1
#define NSIG   12
#define NBATCH 64
#define NLAG   51        // 2*25 + 1
#define NTAU   26        // tau = 0..25
#define NPAIR  78        // 12*13/2 unique (n<=m) pairs
#define NS     9         // frequency slices (144 CTAs = one wave on 148 SMs)
#define CH     114       // folded freqs per slice (9*114 = 1026 >= 1025)
#define BPG    4         // batches per gcc CTA
#define GCC_BLOCK 320    // 4 batch-groups x 80 threads (78 active pairs each)
#define FFT_BLOCK 128
#define OUTB   (NSIG*NSIG*NLAG)   // 7344 floats per batch

// -------- device scratch (static: no allocations allowed) --------
__device__ float2 g_dft2[36 * 64];                // (c,s) of 2*pi*j*a/64, rows j=0..35
__device__ float4 g_dft4[36 * 64];                // (c,c,s,s) duplicated-pair form
__device__ float2 g_spec[NBATCH * NSIG * NFREQ];  // PHAT-normalized spectra
__device__ unsigned long long g_part2[NS][NBATCH][NPAIR][NTAU];  // packed (g+, g-)

// -------- packed fp32x2 helpers --------
__device__ __forceinline__ unsigned long long fma_x2(unsigned long long a,
                                                     unsigned long long b,
                                                     unsigned long long c) {
    unsigned long long d;
    asm("fma.rn.f32x2 %0, %1, %2, %3;" : "=l"(d) : "l"(a), "l"(b), "l"(c));
    return d;
}
__device__ __forceinline__ unsigned long long pack2(float lo, float hi) {
    unsigned long long d;
    asm("mov.b64 %0, {%1, %2};" : "=l"(d) : "f"(lo), "f"(hi));
    return d;
}
__device__ __forceinline__ void unpack2(unsigned long long v, float& lo, float& hi) {
    asm("mov.b64 {%0, %1}, %2;" : "=f"(lo), "=f"(hi) : "l"(v));
}

// ================= init: 64-pt DFT tables (both forms) =================
__global__ void init_tables_kernel() {
    int t = blockIdx.x * blockDim.x + threadIdx.x;
    int stride = gridDim.x * blockDim.x;
    for (int i = t; i < 36 * 64; i += stride) {
        int j = i >> 6, a = i & 63;
        float s, c;
        sincospif((float)(j * a) * (1.0f / 32.0f), &s, &c);   // 2*pi*j*a/64
        g_dft2[i] = make_float2(c, s);
        g_dft4[i] = make_float4(c, c, s, s);
    }
}

// ================= FFT (64x64 four-step, fully folded, 2x register-tiled) + PHAT =====
// x[k], k = 64*a + b. Stage 1 (a-folded real DFT, d<=32, Hermitian mirror to 64-d),
// stage 2 (b-folded 64-pt DFT over columns). Y stored as SoA floats with stride 65
// (odd word stride => conflict-free for both lane-b writes and lane-d reads).
// 128 threads: each owns 2 b-columns (stage 1) and 2 d-rows (stage 2), 9 outputs each.
__global__ __launch_bounds__(FFT_BLOCK) void fft_phat_kernel(const float* __restrict__ x) {
    extern __shared__ float smem[];
    float2* xf    = (float2*)smem;              // [32][64]: (xe,xo); a=0 -> (x0,x32)
    float*  Yr    = (float*)(xf + 32 * 64);     // [64][65]  (row b, col d)
    float*  Yi    = Yr + 64 * 65;
    float2* dft2s = (float2*)(Yi + 64 * 65);    // [36][64] (c,s)
    float4* dft4s = (float4*)(dft2s + 36 * 64); // [36][64] (c,c,s,s)

    const int t = threadIdx.x;
    const float* xin = x + (size_t)blockIdx.x * KLEN;

    for (int i = t; i < 36 * 64; i += FFT_BLOCK) {
        dft2s[i] = g_dft2[i];
        dft4s[i] = g_dft4[i];
    }
    for (int i = t; i < 32 * 64; i += FFT_BLOCK) {
        int a = i >> 6, b = i & 63;
        if (a == 0) {
            xf[b] = make_float2(xin[b], xin[32 * 64 + b]);
        } else {
            float v1 = xin[a * 64 + b];
            float v2 = xin[(64 - a) * 64 + b];
            xf[a * 64 + b] = make_float2(v1 + v2, v1 - v2);
        }
    }
    __syncthreads();

    const int lane32 = t & 31, q0 = t >> 5;     // q0 uniform per warp

    // ---- stage 1: 2 b-columns x 9 d's, packed (yr, yi) accumulators ----
    {
        const int b0 = lane32, b1 = lane32 + 32;
        unsigned long long acc0[9], acc1[9];
        #pragma unroll
        for (int i = 0; i < 9; i++) { acc0[i] = 0ull; acc1[i] = 0ull; }

        for (int a = 1; a < 32; a++) {
            float2 v0 = xf[a * 64 + b0];
            float2 v1 = xf[a * 64 + b1];
            unsigned long long vp0 = pack2(v0.x, -v0.y);
            unsigned long long vp1 = pack2(v1.x, -v1.y);
            const float2* col = dft2s + a;
            #pragma unroll
            for (int i = 0; i < 9; i++) {
                int d = q0 + 4 * i;                 // d<=35; padded rows, junk discarded
                unsigned long long cs = *(const unsigned long long*)(col + d * 64);
                acc0[i] = fma_x2(vp0, cs, acc0[i]);
                acc1[i] = fma_x2(vp1, cs, acc1[i]);
            }
        }

        #pragma unroll
        for (int h = 0; h < 2; h++) {
            const int b = lane32 + 32 * h;
            unsigned long long* acc = h ? acc1 : acc0;
            float2 e = dft2s[64 + b];        // (cos,sin)(2*pi*b/64)
            float2 x03 = xf[b];              // (x0, x32)
            #pragma unroll
            for (int i = 0; i < 9; i++) {
                int d = q0 + 4 * i;
                if (d <= 32) {
                    float yr, yi;
                    unpack2(acc[i], yr, yi);
                    yr += x03.x + ((d & 1) ? -x03.y : x03.y);
                    float s, c;
                    sincospif((float)(b * d) * (1.0f / 2048.0f), &s, &c); // W4096^{bd}
                    Yr[b * 65 + d] = yr * c + yi * s;
                    Yi[b * 65 + d] = yi * c - yr * s;
                    if (d >= 1 && d <= 31) {
                        float tmr = e.x * c + e.y * s;     // cos(2pi b/64 - th)
                        float tms = e.y * c - e.x * s;     // sin(2pi b/64 - th)
                        Yr[b * 65 + (64 - d)] = yr * tmr - yi * tms;
                        Yi[b * 65 + (64 - d)] = -(yr * tms + yi * tmr);
                    }
                }
            }
        }
    }
    __syncthreads();

    // ---- stage 2: 2 d-rows x 9 cc's; b-folded; packed (Xr, Xi) accumulators ----
    {
        const int d0 = lane32, d1 = lane32 + 32;
        unsigned long long acc0[9], acc1[9];

        #pragma unroll
        for (int k = 0; k < 2; k++) {
            int dd = (k ? d1 : d0);
            float z0r = Yr[dd],           z0i = Yi[dd];            // b=0
            float z32r = Yr[32 * 65 + dd], z32i = Yi[32 * 65 + dd]; // b=32
            #pragma unroll
            for (int j = 0; j < 9; j++) {
                int cc = q0 + 4 * j;
                float sg = (cc & 1) ? -1.f : 1.f;
                unsigned long long v = pack2(z0r + sg * z32r, z0i + sg * z32i);
                if (k) acc1[j] = v; else acc0[j] = v;
            }
        }

        for (int b = 1; b < 32; b++) {
            float z1r0 = Yr[b * 65 + d0],        z1i0 = Yi[b * 65 + d0];
            float z2r0 = Yr[(64 - b) * 65 + d0], z2i0 = Yi[(64 - b) * 65 + d0];
            float z1r1 = Yr[b * 65 + d1],        z1i1 = Yi[b * 65 + d1];
            float z2r1 = Yr[(64 - b) * 65 + d1], z2i1 = Yi[(64 - b) * 65 + d1];
            // Xr += zex*c + zoy*s ;  Xi += zey*c - zox*s
            unsigned long long pe0 = pack2(z1r0 + z2r0, z1i0 + z2i0);
            unsigned long long po0 = pack2(z1i0 - z2i0, -(z1r0 - z2r0));
            unsigned long long pe1 = pack2(z1r1 + z2r1, z1i1 + z2i1);
            unsigned long long po1 = pack2(z1i1 - z2i1, -(z1r1 - z2r1));
            const float4* col = dft4s + b;
            #pragma unroll
            for (int j = 0; j < 9; j++) {
                int cc = q0 + 4 * j;                 // <=35; padded rows, junk discarded
                longlong2 w = *(const longlong2*)(col + cc * 64); // (c,c),(s,s) bcast
                acc0[j] = fma_x2(pe0, (unsigned long long)w.x, acc0[j]);
                acc0[j] = fma_x2(po0, (unsigned long long)w.y, acc0[j]);
                acc1[j] = fma_x2(pe1, (unsigned long long)w.x, acc1[j]);
                acc1[j] = fma_x2(po1, (unsigned long long)w.y, acc1[j]);
            }
        }

        float2* outp = g_spec + (size_t)blockIdx.x * NFREQ;
        #pragma unroll
        for (int k = 0; k < 2; k++) {
            int dd = (k ? d1 : d0);
            #pragma unroll
            for (int j = 0; j < 9; j++) {
                int cc = q0 + 4 * j;
                int f = cc * 64 + dd;
                if (cc <= 32 && f <= 2048) {
                    float Xr, Xi;
                    unpack2(k ? acc1[j] : acc0[j], Xr, Xi);
                    float mag = sqrtf(Xr * Xr + Xi * Xi);
                    float inv = 1.0f / (mag + 1e-12f);
                    outp[f] = make_float2(Xr * inv, Xi * inv);
                }
            }
        }
    }
}

// ================= GCC: folded cross-spectrum x lag twiddles (f32x2 packed) ==========
// grid (16 batch-groups, 9 slices), block 320 = 4 x 80. Each 80-thread group handles
// one batch: thread = one pair, all 26 taus, 114-freq slice. Lag twiddles generated
// in-kernel via sincospif (exact int args < 2^24). Register accumulators, no atomics.
__global__ __launch_bounds__(GCC_BLOCK) void gcc_kernel() {
    extern __shared__ float smem[];
    float2* suA = (float2*)smem;                     // [BPG][12][CH] spectra at f
    float2* suB = suA + BPG * NSIG * CH;             // [BPG][12][CH] spectra at 2048-f
    float4* T   = (float4*)(suB + BPG * NSIG * CH);  // [CH][26] (wc,wc,ws,ws)

    const int t = threadIdx.x;
    const int bg = blockIdx.x;
    const int f0 = blockIdx.y * CH;

    for (int i = t; i < BPG * NSIG * CH; i += GCC_BLOCK) {
        int g = i / (NSIG * CH);
        int r = i - g * (NSIG * CH);
        int sig = r / CH, hl = r - sig * CH;
        int f = f0 + hl;
        const float2* sp = g_spec + ((size_t)(bg * BPG + g) * NSIG + sig) * NFREQ;
        suA[i] = (f <= 1024) ? sp[f] : make_float2(0.f, 0.f);
        suB[i] = (f <= 1023) ? sp[2048 - f] : make_float2(0.f, 0.f);
    }
    for (int i = t; i < CH * NTAU; i += GCC_BLOCK) {
        int hl = i / NTAU, tau = i - hl * NTAU;
        int f = f0 + hl;
        if (f <= 1024) {
            float s, c;
            sincospif((float)(f * tau) * (1.0f / 2048.0f), &s, &c);
            float w = ((f == 0) ? 1.0f : 2.0f) * (1.0f / (float)KLEN);
            T[i] = make_float4(w * c, w * c, w * s, w * s);
        } else {
            T[i] = make_float4(0.f, 0.f, 0.f, 0.f);
        }
    }
    __syncthreads();

    const int g = t / 80, u = t - g * 80;
    if (u >= NPAIR) return;

    int n = 0, rem = u;
    #pragma unroll
    for (int k = 0; k < NSIG; k++) {
        int cnt = NSIG - k;
        if (rem < cnt) { n = k; break; }
        rem -= cnt;
    }
    const int m = n + rem;

    const float2* bA = suA + g * (NSIG * CH);
    const float2* bB = suB + g * (NSIG * CH);
    const float2* pAn = bA + n * CH;
    const float2* pAm = bA + m * CH;
    const float2* pBn = bB + n * CH;
    const float2* pBm = bB + m * CH;

    unsigned long long acc[NTAU];   // packed (g+, g-)
    #pragma unroll
    for (int i = 0; i < NTAU; i++) acc[i] = 0ull;

    for (int hl = 0; hl < CH; hl++) {
        float2 a1 = pAn[hl], b1 = pAm[hl];
        float2 a2 = pBn[hl], b2 = pBm[hl];
        float U1 = a1.x * b1.x + a1.y * b1.y;
        float V1 = a1.y * b1.x - a1.x * b1.y;
        float U2 = a2.x * b2.x + a2.y * b2.y;
        float V2 = a2.y * b2.x - a2.x * b2.y;
        float Ue = U1 + U2, Uo = U1 - U2;
        float Vme = V1 - V2, Vpo = V1 + V2;
        unsigned long long pUe = pack2(Ue, Ue);
        unsigned long long pUo = pack2(Uo, Uo);
        unsigned long long pVe = pack2(-Vme, Vme);
        unsigned long long pVo = pack2(-Vpo, Vpo);
        const longlong2* tw = (const longlong2*)(T + (size_t)hl * NTAU);
        #pragma unroll
        for (int tau = 0; tau < NTAU; tau++) {
            longlong2 w = tw[tau];   // .x = (wc,wc), .y = (ws,ws)
            acc[tau] = fma_x2((unsigned long long)w.x, (tau & 1) ? pUo : pUe, acc[tau]);
            acc[tau] = fma_x2((unsigned long long)w.y, (tau & 1) ? pVo : pVe, acc[tau]);
        }
    }

    unsigned long long* pr = &g_part2[blockIdx.y][bg * BPG + g][u][0];
    #pragma unroll
    for (int tau = 0; tau < NTAU; tau++) pr[tau] = acc[tau];
}

// ================= reduce partials + triangular mirror expansion =================
// thread = (batch, pair, tau-pair); 16B loads, sums 9 slices, writes up to 8 floats.
__global__ void reduce_kernel(float* __restrict__ out) {
    int i = blockIdx.x * blockDim.x + threadIdx.x;
    if (i >= NBATCH * NPAIR * 13) return;
    int b = i / (NPAIR * 13);
    int r = i - b * (NPAIR * 13);
    int p = r / 13, k2 = r - p * 13;
    int tau0 = 2 * k2, tau1 = tau0 + 1;

    float gp0 = 0.f, gm0 = 0.f, gp1 = 0.f, gm1 = 0.f;
    #pragma unroll
    for (int s = 0; s < NS; s++) {
        ulonglong2 v = *(const ulonglong2*)&g_part2[s][b][p][tau0];
        float lo, hi;
        unpack2(v.x, lo, hi); gp0 += lo; gm0 += hi;
        unpack2(v.y, lo, hi); gp1 += lo; gm1 += hi;
    }

    int n = 0, rem = p;
    #pragma unroll
    for (int k = 0; k < NSIG; k++) {
        int cnt = NSIG - k;
        if (rem < cnt) { n = k; break; }
        rem -= cnt;
    }
    int m = n + rem;

    float* ob  = out + (size_t)b * OUTB;
    float* onm = ob + (n * NSIG + m) * NLAG;
    onm[tau0] = gp0;
    onm[tau1] = gp1;
    if (tau0 > 0) onm[NLAG - tau0] = gm0;
    onm[NLAG - tau1] = gm1;
    if (n != m) {
        float* omn = ob + (m * NSIG + n) * NLAG;
        omn[tau0] = gm0;
        omn[tau1] = gm1;
        if (tau0 > 0) omn[NLAG - tau0] = gp0;
        omn[NLAG - tau1] = gp1;
    }
}

// ================= launch =================
extern "C" void kernel_launch(void* const* d_in, const int* in_sizes, int n_in,
                              void* d_out, int out_size) {
    const float* x = (const float*)d_in[0];
    float* out = (float*)d_out;

    const int fft_smem = 32 * 64 * (int)sizeof(float2)      // xf
                       + 2 * 64 * 65 * (int)sizeof(float)   // Yr, Yi
                       + 36 * 64 * (int)sizeof(float2)      // dft2s
                       + 36 * 64 * (int)sizeof(float4);     // dft4s  = 104,960 B
    const int gcc_smem = 2 * BPG * NSIG * CH * (int)sizeof(float2)
                       + CH * NTAU * (int)sizeof(float4);   // 134,976 B

    cudaFuncSetAttribute(fft_phat_kernel, cudaFuncAttributeMaxDynamicSharedMemorySize, fft_smem);
    cudaFuncSetAttribute(gcc_kernel,      cudaFuncAttributeMaxDynamicSharedMemorySize, gcc_smem);

    init_tables_kernel<<<18, 128>>>();
    fft_phat_kernel<<<NBATCH * NSIG, FFT_BLOCK, fft_smem>>>(x);
    gcc_kernel<<<dim3(NBATCH / BPG, NS), GCC_BLOCK, gcc_smem>>>();
    const int rthreads = NBATCH * NPAIR * 13;
    reduce_kernel<<<(rthreads + 255) / 256, 256>>>(out);
}

// round 6
// speedup vs baseline: 1.1289x; 1.1289x over previous
#include <cuda_runtime.h>
#include <math.h>

#define KLEN   4096
#define NFREQ  2049      // K/2 + 1
#define NH     1025      // folded freqs h=0..1024 (f=h pairs with f=2048-h)
#define NSIG   12
#define NBATCH 64
#define NLAG   51        // 2*25 + 1
#define NTAU   26        // tau = 0..25
#define NPAIR  78        // 12*13/2 unique (n<=m) pairs
#define NS     9         // frequency slices (144 CTAs = one wave on 148 SMs)
#define CH     114       // folded freqs per slice (9*114 = 1026 >= 1025)
#define BPG    4         // batches per gcc CTA
#define GCC_BLOCK 320    // 4 batch-groups x 80 threads (78 active pairs each)
#define OUTB   (NSIG*NSIG*NLAG)   // 7344 floats per batch

// -------- device scratch (static: no allocations allowed) --------
__device__ float2 g_dft2[36 * 64];                // (c,s) of 2*pi*j*a/64, rows j=0..35
__device__ float4 g_lag4[NH * NTAU];              // (w*c, w*c, w*s, w*s) at [h*26+tau]
__device__ float2 g_spec[NBATCH * NSIG * NFREQ];  // PHAT-normalized spectra
__device__ unsigned long long g_part2[NS][NBATCH][NPAIR][NTAU];  // packed (g+, g-)

// -------- packed fp32x2 helpers --------
__device__ __forceinline__ unsigned long long fma_x2(unsigned long long a,
                                                     unsigned long long b,
                                                     unsigned long long c) {
    unsigned long long d;
    asm("fma.rn.f32x2 %0, %1, %2, %3;" : "=l"(d) : "l"(a), "l"(b), "l"(c));
    return d;
}
__device__ __forceinline__ unsigned long long pack2(float lo, float hi) {
    unsigned long long d;
    asm("mov.b64 %0, {%1, %2};" : "=l"(d) : "f"(lo), "f"(hi));
    return d;
}
__device__ __forceinline__ void unpack2(unsigned long long v, float& lo, float& hi) {
    asm("mov.b64 {%0, %1}, %2;" : "=f"(lo), "=f"(hi) : "l"(v));
}

// ================= init: twiddle tables =================
__global__ void init_tables_kernel() {
    int t = blockIdx.x * blockDim.x + threadIdx.x;
    int stride = gridDim.x * blockDim.x;
    for (int i = t; i < 36 * 64; i += stride) {
        int j = i >> 6, a = i & 63;
        float s, c;
        sincospif((float)(j * a) * (1.0f / 32.0f), &s, &c);   // 2*pi*j*a/64
        g_dft2[i] = make_float2(c, s);
    }
    for (int i = t; i < NH * NTAU; i += stride) {
        int h = i / NTAU, tau = i - h * NTAU;
        float s, c;
        sincospif((float)(h * tau) * (1.0f / 2048.0f), &s, &c); // 2*pi*h*tau/4096
        float w = ((h == 0) ? 1.0f : 2.0f) * (1.0f / (float)KLEN);
        g_lag4[i] = make_float4(w * c, w * c, w * s, w * s);
    }
}

// ================= FFT (64x64 four-step, fully folded, register-blocked) + PHAT ======
// Identical structure to the round-4 winner (256 threads, 9 outputs/thread, 3 CTAs/SM);
// ONLY change: Y stored SoA (Yr/Yi) with odd word stride 65 -> conflict-free STS in
// stage 1 (lane-varying b) and conflict-free LDS in stage 2 (lane-varying d).
__global__ __launch_bounds__(256) void fft_phat_kernel(const float* __restrict__ x) {
    extern __shared__ float smem[];
    float2* xf  = (float2*)smem;            // [32][64]: (xe,xo); a=0 -> (x0,x32)
    float*  Yr  = (float*)(xf + 32 * 64);   // [64 b][65] (col d), odd stride
    float*  Yi  = Yr + 64 * 65;
    float2* dft = (float2*)(Yi + 64 * 65);  // rows j=0..32 valid; padded to 36 rows

    const int t = threadIdx.x;
    const float* xin = x + (size_t)blockIdx.x * KLEN;

    for (int i = t; i < 36 * 64; i += 256) dft[i] = g_dft2[i];
    for (int i = t; i < 32 * 64; i += 256) {
        int a = i >> 6, b = i & 63;
        if (a == 0) {
            xf[b] = make_float2(xin[b], xin[32 * 64 + b]);
        } else {
            float v1 = xin[a * 64 + b];
            float v2 = xin[(64 - a) * 64 + b];
            xf[a * 64 + b] = make_float2(v1 + v2, v1 - v2);
        }
    }
    __syncthreads();

    const int bb = t & 63, q0 = t >> 6;

    // ---- stage 1: 9 packed accumulators (yr, yi) for d = q0 + 4i ----
    {
        unsigned long long acc[9];
        #pragma unroll
        for (int i = 0; i < 9; i++) acc[i] = 0ull;

        for (int a = 1; a < 32; a++) {
            float2 v = xf[a * 64 + bb];
            unsigned long long vp = pack2(v.x, -v.y);
            const float2* col = dft + a;
            #pragma unroll
            for (int i = 0; i < 9; i++) {
                int d = q0 + 4 * i;                    // d<=35; padded rows, junk discarded
                unsigned long long cs = *(const unsigned long long*)(col + d * 64);
                acc[i] = fma_x2(vp, cs, acc[i]);
            }
        }

        float2 e = dft[64 + bb];       // (cos, sin)(2*pi*b/64)
        float2 x03 = xf[bb];           // (x0, x32)
        #pragma unroll
        for (int i = 0; i < 9; i++) {
            int d = q0 + 4 * i;
            if (d <= 32) {
                float yr, yi;
                unpack2(acc[i], yr, yi);
                yr += x03.x + ((d & 1) ? -x03.y : x03.y);
                float s, c;
                sincospif((float)(bb * d) * (1.0f / 2048.0f), &s, &c); // W4096^{bd}=c-is
                Yr[bb * 65 + d] = yr * c + yi * s;
                Yi[bb * 65 + d] = yi * c - yr * s;
                if (d >= 1 && d <= 31) {
                    float tmr = e.x * c + e.y * s;     // cos(2pi b/64 - th)
                    float tms = e.y * c - e.x * s;     // sin(2pi b/64 - th)
                    Yr[bb * 65 + (64 - d)] = yr * tmr - yi * tms;
                    Yi[bb * 65 + (64 - d)] = -(yr * tms + yi * tmr);
                }
            }
        }
    }
    __syncthreads();

    // ---- stage 2: d = bb, cc = q0 + 4j; b-folded, 9 complex accumulators ----
    {
        const int d = bb;
        float Xr[9], Xi[9];
        float z0r = Yr[d],           z0i = Yi[d];
        float z32r = Yr[32 * 65 + d], z32i = Yi[32 * 65 + d];
        #pragma unroll
        for (int j = 0; j < 9; j++) {
            int cc = q0 + 4 * j;
            float sg = (cc & 1) ? -1.f : 1.f;
            Xr[j] = z0r + sg * z32r;
            Xi[j] = z0i + sg * z32i;
        }

        for (int b = 1; b < 32; b++) {
            float z1r = Yr[b * 65 + d],        z1i = Yi[b * 65 + d];
            float z2r = Yr[(64 - b) * 65 + d], z2i = Yi[(64 - b) * 65 + d];
            float zex = z1r + z2r, zey = z1i + z2i;
            float zox = z1r - z2r, zoy = z1i - z2i;
            const float2* col = dft + b;
            #pragma unroll
            for (int j = 0; j < 9; j++) {
                int cc = q0 + 4 * j;                   // <=35; padded rows, junk discarded
                float2 cs = col[cc * 64];
                Xr[j] += zex * cs.x + zoy * cs.y;
                Xi[j] += zey * cs.x - zox * cs.y;
            }
        }

        float2* outp = g_spec + (size_t)blockIdx.x * NFREQ;
        #pragma unroll
        for (int j = 0; j < 9; j++) {
            int cc = q0 + 4 * j;
            int f = cc * 64 + d;
            if (cc <= 32 && f <= 2048) {
                float mag = sqrtf(Xr[j] * Xr[j] + Xi[j] * Xi[j]);
                float inv = 1.0f / (mag + 1e-12f);
                outp[f] = make_float2(Xr[j] * inv, Xi[j] * inv);
            }
        }
    }
}

// ================= GCC: folded cross-spectrum x lag twiddles (f32x2 packed) ==========
// grid (16 batch-groups, 9 slices), block 320 = 4 x 80. Each 80-thread group handles
// one batch: thread = one pair, all 26 taus, 114-freq slice. Precomputed twiddle table
// (L2-cached) — in-kernel sincospif costs ~7us/wave in MUFU, reverted.
__global__ __launch_bounds__(GCC_BLOCK) void gcc_kernel() {
    extern __shared__ float smem[];
    float2* suA = (float2*)smem;                     // [BPG][12][CH] spectra at f
    float2* suB = suA + BPG * NSIG * CH;             // [BPG][12][CH] spectra at 2048-f
    float4* T   = (float4*)(suB + BPG * NSIG * CH);  // [CH][26] (wc,wc,ws,ws)

    const int t = threadIdx.x;
    const int bg = blockIdx.x;
    const int f0 = blockIdx.y * CH;

    for (int i = t; i < BPG * NSIG * CH; i += GCC_BLOCK) {
        int g = i / (NSIG * CH);
        int r = i - g * (NSIG * CH);
        int sig = r / CH, hl = r - sig * CH;
        int f = f0 + hl;
        const float2* sp = g_spec + ((size_t)(bg * BPG + g) * NSIG + sig) * NFREQ;
        suA[i] = (f <= 1024) ? sp[f] : make_float2(0.f, 0.f);
        suB[i] = (f <= 1023) ? sp[2048 - f] : make_float2(0.f, 0.f);
    }
    for (int i = t; i < CH * NTAU; i += GCC_BLOCK) {
        int hl = i / NTAU;
        int f = f0 + hl;
        T[i] = (f <= 1024) ? g_lag4[f * NTAU + (i - hl * NTAU)]
                           : make_float4(0.f, 0.f, 0.f, 0.f);
    }
    __syncthreads();

    const int g = t / 80, u = t - g * 80;
    if (u >= NPAIR) return;

    int n = 0, rem = u;
    #pragma unroll
    for (int k = 0; k < NSIG; k++) {
        int cnt = NSIG - k;
        if (rem < cnt) { n = k; break; }
        rem -= cnt;
    }
    const int m = n + rem;

    const float2* bA = suA + g * (NSIG * CH);
    const float2* bB = suB + g * (NSIG * CH);
    const float2* pAn = bA + n * CH;
    const float2* pAm = bA + m * CH;
    const float2* pBn = bB + n * CH;
    const float2* pBm = bB + m * CH;

    unsigned long long acc[NTAU];   // packed (g+, g-)
    #pragma unroll
    for (int i = 0; i < NTAU; i++) acc[i] = 0ull;

    for (int hl = 0; hl < CH; hl++) {
        float2 a1 = pAn[hl], b1 = pAm[hl];
        float2 a2 = pBn[hl], b2 = pBm[hl];
        float U1 = a1.x * b1.x + a1.y * b1.y;
        float V1 = a1.y * b1.x - a1.x * b1.y;
        float U2 = a2.x * b2.x + a2.y * b2.y;
        float V2 = a2.y * b2.x - a2.x * b2.y;
        float Ue = U1 + U2, Uo = U1 - U2;
        float Vme = V1 - V2, Vpo = V1 + V2;
        unsigned long long pUe = pack2(Ue, Ue);
        unsigned long long pUo = pack2(Uo, Uo);
        unsigned long long pVe = pack2(-Vme, Vme);
        unsigned long long pVo = pack2(-Vpo, Vpo);
        const longlong2* tw = (const longlong2*)(T + (size_t)hl * NTAU);
        #pragma unroll
        for (int tau = 0; tau < NTAU; tau++) {
            longlong2 w = tw[tau];   // .x = (wc,wc), .y = (ws,ws)
            acc[tau] = fma_x2((unsigned long long)w.x, (tau & 1) ? pUo : pUe, acc[tau]);
            acc[tau] = fma_x2((unsigned long long)w.y, (tau & 1) ? pVo : pVe, acc[tau]);
        }
    }

    unsigned long long* pr = &g_part2[blockIdx.y][bg * BPG + g][u][0];
    #pragma unroll
    for (int tau = 0; tau < NTAU; tau++) pr[tau] = acc[tau];
}

// ================= reduce partials + triangular mirror expansion =================
// thread = (batch, pair, tau-pair); 16B loads, sums 9 slices, writes up to 8 floats.
__global__ void reduce_kernel(float* __restrict__ out) {
    int i = blockIdx.x * blockDim.x + threadIdx.x;
    if (i >= NBATCH * NPAIR * 13) return;
    int b = i / (NPAIR * 13);
    int r = i - b * (NPAIR * 13);
    int p = r / 13, k2 = r - p * 13;
    int tau0 = 2 * k2, tau1 = tau0 + 1;

    float gp0 = 0.f, gm0 = 0.f, gp1 = 0.f, gm1 = 0.f;
    #pragma unroll
    for (int s = 0; s < NS; s++) {
        ulonglong2 v = *(const ulonglong2*)&g_part2[s][b][p][tau0];
        float lo, hi;
        unpack2(v.x, lo, hi); gp0 += lo; gm0 += hi;
        unpack2(v.y, lo, hi); gp1 += lo; gm1 += hi;
    }

    int n = 0, rem = p;
    #pragma unroll
    for (int k = 0; k < NSIG; k++) {
        int cnt = NSIG - k;
        if (rem < cnt) { n = k; break; }
        rem -= cnt;
    }
    int m = n + rem;

    float* ob  = out + (size_t)b * OUTB;
    float* onm = ob + (n * NSIG + m) * NLAG;
    onm[tau0] = gp0;
    onm[tau1] = gp1;
    if (tau0 > 0) onm[NLAG - tau0] = gm0;
    onm[NLAG - tau1] = gm1;
    if (n != m) {
        float* omn = ob + (m * NSIG + n) * NLAG;
        omn[tau0] = gm0;
        omn[tau1] = gm1;
        if (tau0 > 0) omn[NLAG - tau0] = gp0;
        omn[NLAG - tau1] = gp1;
    }
}

// ================= launch =================
extern "C" void kernel_launch(void* const* d_in, const int* in_sizes, int n_in,
                              void* d_out, int out_size) {
    const float* x = (const float*)d_in[0];
    float* out = (float*)d_out;

    const int fft_smem = 32 * 64 * (int)sizeof(float2)      // xf       16,384
                       + 2 * 64 * 65 * (int)sizeof(float)   // Yr, Yi   33,280
                       + 36 * 64 * (int)sizeof(float2);     // dft      18,432 => 68,096
    const int gcc_smem = 2 * BPG * NSIG * CH * (int)sizeof(float2)
                       + CH * NTAU * (int)sizeof(float4);   // 134,976

    cudaFuncSetAttribute(fft_phat_kernel, cudaFuncAttributeMaxDynamicSharedMemorySize, fft_smem);
    cudaFuncSetAttribute(gcc_kernel,      cudaFuncAttributeMaxDynamicSharedMemorySize, gcc_smem);

    init_tables_kernel<<<128, 256>>>();
    fft_phat_kernel<<<NBATCH * NSIG, 256, fft_smem>>>(x);
    gcc_kernel<<<dim3(NBATCH / BPG, NS), GCC_BLOCK, gcc_smem>>>();
    const int rthreads = NBATCH * NPAIR * 13;
    reduce_kernel<<<(rthreads + 255) / 256, 256>>>(out);
}

// round 7
// speedup vs baseline: 1.3793x; 1.2219x over previous
#include <cuda_runtime.h>
#include <math.h>

#define KLEN   4096
#define NFREQ  2049      // K/2 + 1
#define NH     1025      // folded freqs h=0..1024 (f=h pairs with f=2048-h)
#define NSIG   12
#define NBATCH 64
#define NLAG   51        // 2*25 + 1
#define NTAU   26        // tau = 0..25
#define NTP    13        // tau pairs (even, odd)
#define NPAIR  78        // 12*13/2 unique (n<=m) pairs
#define NS     9         // frequency slices (144 CTAs)
#define CH     114       // folded freqs per slice (9*114 = 1026 >= 1025)
#define CHP    115       // padded smem stride (bank-conflict-free su loads)
#define BPG    4         // batches per gcc CTA
#define GCC_BLOCK 320    // 4 batch-groups x 80 threads (78 active pairs each)
#define OUTB   (NSIG*NSIG*NLAG)   // 7344 floats per batch

// -------- device scratch (static: no allocations allowed) --------
__device__ float2 g_dft2[36 * 64];                // (c,s) of 2*pi*j*a/64, rows j=0..35
__device__ float4 g_lagp[NH * NTP];               // (wcE, wcO, wsE, wsO) at [h*13+tp]
__device__ float2 g_spec[NBATCH * NSIG * NFREQ];  // PHAT-normalized spectra
__device__ unsigned long long g_part2[NS][NBATCH][NPAIR][NTAU];  // packed (g+, g-)

// -------- packed fp32x2 helpers --------
__device__ __forceinline__ unsigned long long fma_x2(unsigned long long a,
                                                     unsigned long long b,
                                                     unsigned long long c) {
    unsigned long long d;
    asm("fma.rn.f32x2 %0, %1, %2, %3;" : "=l"(d) : "l"(a), "l"(b), "l"(c));
    return d;
}
__device__ __forceinline__ unsigned long long pack2(float lo, float hi) {
    unsigned long long d;
    asm("mov.b64 %0, {%1, %2};" : "=l"(d) : "f"(lo), "f"(hi));
    return d;
}
__device__ __forceinline__ void unpack2(unsigned long long v, float& lo, float& hi) {
    asm("mov.b64 {%0, %1}, %2;" : "=f"(lo), "=f"(hi) : "l"(v));
}

// ================= init: twiddle tables =================
__global__ void init_tables_kernel() {
    int t = blockIdx.x * blockDim.x + threadIdx.x;
    int stride = gridDim.x * blockDim.x;
    for (int i = t; i < 36 * 64; i += stride) {
        int j = i >> 6, a = i & 63;
        float s, c;
        sincospif((float)(j * a) * (1.0f / 32.0f), &s, &c);   // 2*pi*j*a/64
        g_dft2[i] = make_float2(c, s);
    }
    for (int i = t; i < NH * NTP; i += stride) {
        int h = i / NTP, tp = i - h * NTP;
        int tau0 = 2 * tp, tau1 = tau0 + 1;
        float s0, c0, s1, c1;
        sincospif((float)(h * tau0) * (1.0f / 2048.0f), &s0, &c0);
        sincospif((float)(h * tau1) * (1.0f / 2048.0f), &s1, &c1);
        float w = ((h == 0) ? 1.0f : 2.0f) * (1.0f / (float)KLEN);
        g_lagp[i] = make_float4(w * c0, w * c1, w * s0, w * s1);
    }
}

// ================= FFT (64x64 four-step, fully folded, register-blocked) + PHAT ======
// Unchanged from the 98.3us baseline (256 threads, SoA Y stride 65, 3 CTAs/SM).
__global__ __launch_bounds__(256) void fft_phat_kernel(const float* __restrict__ x) {
    extern __shared__ float smem[];
    float2* xf  = (float2*)smem;            // [32][64]: (xe,xo); a=0 -> (x0,x32)
    float*  Yr  = (float*)(xf + 32 * 64);   // [64 b][65] (col d), odd stride
    float*  Yi  = Yr + 64 * 65;
    float2* dft = (float2*)(Yi + 64 * 65);  // rows j=0..32 valid; padded to 36 rows

    const int t = threadIdx.x;
    const float* xin = x + (size_t)blockIdx.x * KLEN;

    for (int i = t; i < 36 * 64; i += 256) dft[i] = g_dft2[i];
    for (int i = t; i < 32 * 64; i += 256) {
        int a = i >> 6, b = i & 63;
        if (a == 0) {
            xf[b] = make_float2(xin[b], xin[32 * 64 + b]);
        } else {
            float v1 = xin[a * 64 + b];
            float v2 = xin[(64 - a) * 64 + b];
            xf[a * 64 + b] = make_float2(v1 + v2, v1 - v2);
        }
    }
    __syncthreads();

    const int bb = t & 63, q0 = t >> 6;

    // ---- stage 1: 9 packed accumulators (yr, yi) for d = q0 + 4i ----
    {
        unsigned long long acc[9];
        #pragma unroll
        for (int i = 0; i < 9; i++) acc[i] = 0ull;

        for (int a = 1; a < 32; a++) {
            float2 v = xf[a * 64 + bb];
            unsigned long long vp = pack2(v.x, -v.y);
            const float2* col = dft + a;
            #pragma unroll
            for (int i = 0; i < 9; i++) {
                int d = q0 + 4 * i;                    // d<=35; padded rows, junk discarded
                unsigned long long cs = *(const unsigned long long*)(col + d * 64);
                acc[i] = fma_x2(vp, cs, acc[i]);
            }
        }

        float2 e = dft[64 + bb];       // (cos, sin)(2*pi*b/64)
        float2 x03 = xf[bb];           // (x0, x32)
        #pragma unroll
        for (int i = 0; i < 9; i++) {
            int d = q0 + 4 * i;
            if (d <= 32) {
                float yr, yi;
                unpack2(acc[i], yr, yi);
                yr += x03.x + ((d & 1) ? -x03.y : x03.y);
                float s, c;
                sincospif((float)(bb * d) * (1.0f / 2048.0f), &s, &c); // W4096^{bd}=c-is
                Yr[bb * 65 + d] = yr * c + yi * s;
                Yi[bb * 65 + d] = yi * c - yr * s;
                if (d >= 1 && d <= 31) {
                    float tmr = e.x * c + e.y * s;     // cos(2pi b/64 - th)
                    float tms = e.y * c - e.x * s;     // sin(2pi b/64 - th)
                    Yr[bb * 65 + (64 - d)] = yr * tmr - yi * tms;
                    Yi[bb * 65 + (64 - d)] = -(yr * tms + yi * tmr);
                }
            }
        }
    }
    __syncthreads();

    // ---- stage 2: d = bb, cc = q0 + 4j; b-folded, 9 complex accumulators ----
    {
        const int d = bb;
        float Xr[9], Xi[9];
        float z0r = Yr[d],           z0i = Yi[d];
        float z32r = Yr[32 * 65 + d], z32i = Yi[32 * 65 + d];
        #pragma unroll
        for (int j = 0; j < 9; j++) {
            int cc = q0 + 4 * j;
            float sg = (cc & 1) ? -1.f : 1.f;
            Xr[j] = z0r + sg * z32r;
            Xi[j] = z0i + sg * z32i;
        }

        for (int b = 1; b < 32; b++) {
            float z1r = Yr[b * 65 + d],        z1i = Yi[b * 65 + d];
            float z2r = Yr[(64 - b) * 65 + d], z2i = Yi[(64 - b) * 65 + d];
            float zex = z1r + z2r, zey = z1i + z2i;
            float zox = z1r - z2r, zoy = z1i - z2i;
            const float2* col = dft + b;
            #pragma unroll
            for (int j = 0; j < 9; j++) {
                int cc = q0 + 4 * j;                   // <=35; padded rows, junk discarded
                float2 cs = col[cc * 64];
                Xr[j] += zex * cs.x + zoy * cs.y;
                Xi[j] += zey * cs.x - zox * cs.y;
            }
        }

        float2* outp = g_spec + (size_t)blockIdx.x * NFREQ;
        #pragma unroll
        for (int j = 0; j < 9; j++) {
            int cc = q0 + 4 * j;
            int f = cc * 64 + d;
            if (cc <= 32 && f <= 2048) {
                float mag = sqrtf(Xr[j] * Xr[j] + Xi[j] * Xi[j]);
                float inv = 1.0f / (mag + 1e-12f);
                outp[f] = make_float2(Xr[j] * inv, Xi[j] * inv);
            }
        }
    }
}

// ================= GCC: folded cross-spectrum x lag twiddles =========================
// (even-tau, odd-tau) lane packing: accU[tp] += (wcE,wcO)*(Ue,Uo),
// accV[tp] += (wsE,wsO)*(Vme,Vpo); epilogue g+/g- = A -/+ B.
// One LDS.128 feeds TWO taus as ready packed operands: 13 LDS + 26 fma_x2 per hl
// (halved from 26 LDS + 52 fma_x2). su stride padded to 115 (conflict-free).
__global__ __launch_bounds__(GCC_BLOCK, 2) void gcc_kernel() {
    extern __shared__ float smem[];
    float2* suA = (float2*)smem;                      // [BPG][12][CHP] spectra at f
    float2* suB = suA + BPG * NSIG * CHP;             // [BPG][12][CHP] spectra at 2048-f
    float4* T   = (float4*)(suB + BPG * NSIG * CHP);  // [CH][13] (wcE,wcO,wsE,wsO)

    const int t = threadIdx.x;
    const int bg = blockIdx.x;
    const int f0 = blockIdx.y * CH;

    for (int i = t; i < BPG * NSIG * CH; i += GCC_BLOCK) {
        int g = i / (NSIG * CH);
        int r = i - g * (NSIG * CH);
        int sig = r / CH, hl = r - sig * CH;
        int f = f0 + hl;
        const float2* sp = g_spec + ((size_t)(bg * BPG + g) * NSIG + sig) * NFREQ;
        int di = (g * NSIG + sig) * CHP + hl;
        suA[di] = (f <= 1024) ? sp[f] : make_float2(0.f, 0.f);
        suB[di] = (f <= 1023) ? sp[2048 - f] : make_float2(0.f, 0.f);
    }
    for (int i = t; i < CH * NTP; i += GCC_BLOCK) {
        int hl = i / NTP;
        int f = f0 + hl;
        T[i] = (f <= 1024) ? g_lagp[f * NTP + (i - hl * NTP)]
                           : make_float4(0.f, 0.f, 0.f, 0.f);
    }
    __syncthreads();

    const int g = t / 80, u = t - g * 80;
    if (u >= NPAIR) return;

    int n = 0, rem = u;
    #pragma unroll
    for (int k = 0; k < NSIG; k++) {
        int cnt = NSIG - k;
        if (rem < cnt) { n = k; break; }
        rem -= cnt;
    }
    const int m = n + rem;

    const float2* bA = suA + g * (NSIG * CHP);
    const float2* bB = suB + g * (NSIG * CHP);
    const float2* pAn = bA + n * CHP;
    const float2* pAm = bA + m * CHP;
    const float2* pBn = bB + n * CHP;
    const float2* pBm = bB + m * CHP;

    unsigned long long accU[NTP], accV[NTP];   // lanes = (even tau, odd tau)
    #pragma unroll
    for (int i = 0; i < NTP; i++) { accU[i] = 0ull; accV[i] = 0ull; }

    for (int hl = 0; hl < CH; hl++) {
        float2 a1 = pAn[hl], b1 = pAm[hl];
        float2 a2 = pBn[hl], b2 = pBm[hl];
        float U1 = a1.x * b1.x + a1.y * b1.y;
        float V1 = a1.y * b1.x - a1.x * b1.y;
        float U2 = a2.x * b2.x + a2.y * b2.y;
        float V2 = a2.y * b2.x - a2.x * b2.y;
        unsigned long long pU = pack2(U1 + U2, U1 - U2);   // (Ue, Uo)
        unsigned long long pV = pack2(V1 - V2, V1 + V2);   // (Vme, Vpo)
        const longlong2* tw = (const longlong2*)(T + (size_t)hl * NTP);
        #pragma unroll
        for (int tp = 0; tp < NTP; tp++) {
            longlong2 w = tw[tp];   // .x = (wcE,wcO), .y = (wsE,wsO)
            accU[tp] = fma_x2((unsigned long long)w.x, pU, accU[tp]);
            accV[tp] = fma_x2((unsigned long long)w.y, pV, accV[tp]);
        }
    }

    unsigned long long* pr = &g_part2[blockIdx.y][bg * BPG + g][u][0];
    #pragma unroll
    for (int tp = 0; tp < NTP; tp++) {
        float aE, aO, bE, bO;
        unpack2(accU[tp], aE, aO);
        unpack2(accV[tp], bE, bO);
        pr[2 * tp]     = pack2(aE - bE, aE + bE);   // (g+, g-) even tau
        pr[2 * tp + 1] = pack2(aO - bO, aO + bO);   // (g+, g-) odd tau
    }
}

// ================= reduce partials + triangular mirror expansion =================
__global__ void reduce_kernel(float* __restrict__ out) {
    int i = blockIdx.x * blockDim.x + threadIdx.x;
    if (i >= NBATCH * NPAIR * 13) return;
    int b = i / (NPAIR * 13);
    int r = i - b * (NPAIR * 13);
    int p = r / 13, k2 = r - p * 13;
    int tau0 = 2 * k2, tau1 = tau0 + 1;

    float gp0 = 0.f, gm0 = 0.f, gp1 = 0.f, gm1 = 0.f;
    #pragma unroll
    for (int s = 0; s < NS; s++) {
        ulonglong2 v = *(const ulonglong2*)&g_part2[s][b][p][tau0];
        float lo, hi;
        unpack2(v.x, lo, hi); gp0 += lo; gm0 += hi;
        unpack2(v.y, lo, hi); gp1 += lo; gm1 += hi;
    }

    int n = 0, rem = p;
    #pragma unroll
    for (int k = 0; k < NSIG; k++) {
        int cnt = NSIG - k;
        if (rem < cnt) { n = k; break; }
        rem -= cnt;
    }
    int m = n + rem;

    float* ob  = out + (size_t)b * OUTB;
    float* onm = ob + (n * NSIG + m) * NLAG;
    onm[tau0] = gp0;
    onm[tau1] = gp1;
    if (tau0 > 0) onm[NLAG - tau0] = gm0;
    onm[NLAG - tau1] = gm1;
    if (n != m) {
        float* omn = ob + (m * NSIG + n) * NLAG;
        omn[tau0] = gm0;
        omn[tau1] = gm1;
        if (tau0 > 0) omn[NLAG - tau0] = gp0;
        omn[NLAG - tau1] = gp1;
    }
}

// ================= launch =================
extern "C" void kernel_launch(void* const* d_in, const int* in_sizes, int n_in,
                              void* d_out, int out_size) {
    const float* x = (const float*)d_in[0];
    float* out = (float*)d_out;

    const int fft_smem = 32 * 64 * (int)sizeof(float2)
                       + 2 * 64 * 65 * (int)sizeof(float)
                       + 36 * 64 * (int)sizeof(float2);     // 68,096 B
    const int gcc_smem = 2 * BPG * NSIG * CHP * (int)sizeof(float2)
                       + CH * NTP * (int)sizeof(float4);    // 88,320 + 23,712 = 112,032 B

    cudaFuncSetAttribute(fft_phat_kernel, cudaFuncAttributeMaxDynamicSharedMemorySize, fft_smem);
    cudaFuncSetAttribute(gcc_kernel,      cudaFuncAttributeMaxDynamicSharedMemorySize, gcc_smem);

    init_tables_kernel<<<128, 256>>>();
    fft_phat_kernel<<<NBATCH * NSIG, 256, fft_smem>>>(x);
    gcc_kernel<<<dim3(NBATCH / BPG, NS), GCC_BLOCK, gcc_smem>>>();
    const int rthreads = NBATCH * NPAIR * 13;
    reduce_kernel<<<(rthreads + 255) / 256, 256>>>(out);
}

// round 8
// speedup vs baseline: 1.3898x; 1.0076x over previous
#include <cuda_runtime.h>
#include <math.h>

#define KLEN   4096
#define NFREQ  2049      // K/2 + 1
#define NH     1025      // folded freqs h=0..1024 (f=h pairs with f=2048-h)
#define NSIG   12
#define NBATCH 64
#define NLAG   51        // 2*25 + 1
#define NTAU   26        // tau = 0..25
#define NTP    13        // tau pairs (even, odd)
#define NPAIR  78        // 12*13/2 unique (n<=m) pairs
#define NS     9         // frequency slices (144 CTAs)
#define CH     114       // folded freqs per slice (9*114 = 1026 >= 1025)
#define CHP    115       // padded smem stride (bank-conflict-free su loads)
#define BPG    4         // batches per gcc CTA
#define GCC_BLOCK 320    // 4 batch-groups x 80 threads (78 active pairs each)
#define OUTB   (NSIG*NSIG*NLAG)   // 7344 floats per batch

// -------- device scratch (static: no allocations allowed) --------
__device__ float2 g_dft2[36 * 64];                // (c,s) of 2*pi*j*a/64, rows j=0..35
__device__ float4 g_lagp[NH * NTP];               // (wcE, wcO, wsE, wsO) at [h*13+tp]
__device__ float2 g_spec[NBATCH * NSIG * NFREQ];  // PHAT-normalized spectra
__device__ unsigned long long g_part2[NS][NBATCH][NPAIR][NTAU];  // packed (g+, g-)

// -------- packed fp32x2 helpers --------
__device__ __forceinline__ unsigned long long fma_x2(unsigned long long a,
                                                     unsigned long long b,
                                                     unsigned long long c) {
    unsigned long long d;
    asm("fma.rn.f32x2 %0, %1, %2, %3;" : "=l"(d) : "l"(a), "l"(b), "l"(c));
    return d;
}
__device__ __forceinline__ unsigned long long pack2(float lo, float hi) {
    unsigned long long d;
    asm("mov.b64 %0, {%1, %2};" : "=l"(d) : "f"(lo), "f"(hi));
    return d;
}
__device__ __forceinline__ void unpack2(unsigned long long v, float& lo, float& hi) {
    asm("mov.b64 {%0, %1}, %2;" : "=f"(lo), "=f"(hi) : "l"(v));
}

// ================= init: twiddle tables =================
__global__ void init_tables_kernel() {
    int t = blockIdx.x * blockDim.x + threadIdx.x;
    int stride = gridDim.x * blockDim.x;
    for (int i = t; i < 36 * 64; i += stride) {
        int j = i >> 6, a = i & 63;
        float s, c;
        sincospif((float)(j * a) * (1.0f / 32.0f), &s, &c);   // 2*pi*j*a/64
        g_dft2[i] = make_float2(c, s);
    }
    for (int i = t; i < NH * NTP; i += stride) {
        int h = i / NTP, tp = i - h * NTP;
        int tau0 = 2 * tp, tau1 = tau0 + 1;
        float s0, c0, s1, c1;
        sincospif((float)(h * tau0) * (1.0f / 2048.0f), &s0, &c0);
        sincospif((float)(h * tau1) * (1.0f / 2048.0f), &s1, &c1);
        float w = ((h == 0) ? 1.0f : 2.0f) * (1.0f / (float)KLEN);
        g_lagp[i] = make_float4(w * c0, w * c1, w * s0, w * s1);
    }
}

// ================= FFT (64x64 four-step, fully folded, x2-unrolled loops) + PHAT =====
// Same math as the 80.5us baseline; ONLY change: reduction loops unrolled by 2 with
// 16-byte broadcast twiddle loads (consecutive a / b are adjacent in each dft row),
// cutting LDS instruction issue ~40%. FMA order unchanged -> bitwise-identical output.
__global__ __launch_bounds__(256) void fft_phat_kernel(const float* __restrict__ x) {
    extern __shared__ float smem[];
    float2* xf  = (float2*)smem;            // [32][64]: (xe,xo); a=0 -> (x0,x32)
    float*  Yr  = (float*)(xf + 32 * 64);   // [64 b][65] (col d), odd stride
    float*  Yi  = Yr + 64 * 65;
    float2* dft = (float2*)(Yi + 64 * 65);  // rows j=0..32 valid; padded to 36 rows

    const int t = threadIdx.x;
    const float* xin = x + (size_t)blockIdx.x * KLEN;

    for (int i = t; i < 36 * 64; i += 256) dft[i] = g_dft2[i];
    for (int i = t; i < 32 * 64; i += 256) {
        int a = i >> 6, b = i & 63;
        if (a == 0) {
            xf[b] = make_float2(xin[b], xin[32 * 64 + b]);
        } else {
            float v1 = xin[a * 64 + b];
            float v2 = xin[(64 - a) * 64 + b];
            xf[a * 64 + b] = make_float2(v1 + v2, v1 - v2);
        }
    }
    __syncthreads();

    const int bb = t & 63, q0 = t >> 6;

    // ---- stage 1: 9 packed accumulators (yr, yi) for d = q0 + 4i ----
    {
        unsigned long long acc[9];
        #pragma unroll
        for (int i = 0; i < 9; i++) acc[i] = 0ull;

        // a = 1 (scalar head, keeps pair loads 16B-aligned)
        {
            float2 v = xf[64 + bb];
            unsigned long long vp = pack2(v.x, -v.y);
            #pragma unroll
            for (int i = 0; i < 9; i++) {
                int d = q0 + 4 * i;
                unsigned long long cs = *(const unsigned long long*)(dft + d * 64 + 1);
                acc[i] = fma_x2(vp, cs, acc[i]);
            }
        }
        // a = 2..31 in pairs: one 16B broadcast load gives both packed (c,s)
        for (int a = 2; a < 32; a += 2) {
            float2 v0 = xf[a * 64 + bb];
            float2 v1 = xf[(a + 1) * 64 + bb];
            unsigned long long vp0 = pack2(v0.x, -v0.y);
            unsigned long long vp1 = pack2(v1.x, -v1.y);
            #pragma unroll
            for (int i = 0; i < 9; i++) {
                int d = q0 + 4 * i;                    // d<=35; padded rows, junk discarded
                longlong2 w = *(const longlong2*)(dft + d * 64 + a); // (c_a,s_a),(c_a1,s_a1)
                acc[i] = fma_x2(vp0, (unsigned long long)w.x, acc[i]);
                acc[i] = fma_x2(vp1, (unsigned long long)w.y, acc[i]);
            }
        }

        float2 e = dft[64 + bb];       // (cos, sin)(2*pi*b/64)
        float2 x03 = xf[bb];           // (x0, x32)
        #pragma unroll
        for (int i = 0; i < 9; i++) {
            int d = q0 + 4 * i;
            if (d <= 32) {
                float yr, yi;
                unpack2(acc[i], yr, yi);
                yr += x03.x + ((d & 1) ? -x03.y : x03.y);
                float s, c;
                sincospif((float)(bb * d) * (1.0f / 2048.0f), &s, &c); // W4096^{bd}=c-is
                Yr[bb * 65 + d] = yr * c + yi * s;
                Yi[bb * 65 + d] = yi * c - yr * s;
                if (d >= 1 && d <= 31) {
                    float tmr = e.x * c + e.y * s;     // cos(2pi b/64 - th)
                    float tms = e.y * c - e.x * s;     // sin(2pi b/64 - th)
                    Yr[bb * 65 + (64 - d)] = yr * tmr - yi * tms;
                    Yi[bb * 65 + (64 - d)] = -(yr * tms + yi * tmr);
                }
            }
        }
    }
    __syncthreads();

    // ---- stage 2: d = bb, cc = q0 + 4j; b-folded, x2-unrolled with 16B twiddles ----
    {
        const int d = bb;
        float Xr[9], Xi[9];
        float z0r = Yr[d],           z0i = Yi[d];
        float z32r = Yr[32 * 65 + d], z32i = Yi[32 * 65 + d];
        #pragma unroll
        for (int j = 0; j < 9; j++) {
            int cc = q0 + 4 * j;
            float sg = (cc & 1) ? -1.f : 1.f;
            Xr[j] = z0r + sg * z32r;
            Xi[j] = z0i + sg * z32i;
        }

        // b = 1 (scalar head)
        {
            float z1r = Yr[65 + d],        z1i = Yi[65 + d];
            float z2r = Yr[63 * 65 + d],   z2i = Yi[63 * 65 + d];
            float zex = z1r + z2r, zey = z1i + z2i;
            float zox = z1r - z2r, zoy = z1i - z2i;
            #pragma unroll
            for (int j = 0; j < 9; j++) {
                int cc = q0 + 4 * j;
                float2 cs = dft[cc * 64 + 1];
                Xr[j] += zex * cs.x + zoy * cs.y;
                Xi[j] += zey * cs.x - zox * cs.y;
            }
        }
        // b = 2..31 in pairs
        for (int b = 2; b < 32; b += 2) {
            float z1r0 = Yr[b * 65 + d],          z1i0 = Yi[b * 65 + d];
            float z2r0 = Yr[(64 - b) * 65 + d],   z2i0 = Yi[(64 - b) * 65 + d];
            float z1r1 = Yr[(b + 1) * 65 + d],    z1i1 = Yi[(b + 1) * 65 + d];
            float z2r1 = Yr[(63 - b) * 65 + d],   z2i1 = Yi[(63 - b) * 65 + d];
            float zex0 = z1r0 + z2r0, zey0 = z1i0 + z2i0;
            float zox0 = z1r0 - z2r0, zoy0 = z1i0 - z2i0;
            float zex1 = z1r1 + z2r1, zey1 = z1i1 + z2i1;
            float zox1 = z1r1 - z2r1, zoy1 = z1i1 - z2i1;
            #pragma unroll
            for (int j = 0; j < 9; j++) {
                int cc = q0 + 4 * j;                   // <=35; padded rows, junk discarded
                float4 cs = *(const float4*)(dft + cc * 64 + b); // c_b,s_b,c_b1,s_b1
                Xr[j] += zex0 * cs.x + zoy0 * cs.y;
                Xi[j] += zey0 * cs.x - zox0 * cs.y;
                Xr[j] += zex1 * cs.z + zoy1 * cs.w;
                Xi[j] += zey1 * cs.z - zox1 * cs.w;
            }
        }

        float2* outp = g_spec + (size_t)blockIdx.x * NFREQ;
        #pragma unroll
        for (int j = 0; j < 9; j++) {
            int cc = q0 + 4 * j;
            int f = cc * 64 + d;
            if (cc <= 32 && f <= 2048) {
                float mag = sqrtf(Xr[j] * Xr[j] + Xi[j] * Xi[j]);
                float inv = 1.0f / (mag + 1e-12f);
                outp[f] = make_float2(Xr[j] * inv, Xi[j] * inv);
            }
        }
    }
}

// ================= GCC: folded cross-spectrum x lag twiddles (unchanged) =============
__global__ __launch_bounds__(GCC_BLOCK, 2) void gcc_kernel() {
    extern __shared__ float smem[];
    float2* suA = (float2*)smem;                      // [BPG][12][CHP] spectra at f
    float2* suB = suA + BPG * NSIG * CHP;             // [BPG][12][CHP] spectra at 2048-f
    float4* T   = (float4*)(suB + BPG * NSIG * CHP);  // [CH][13] (wcE,wcO,wsE,wsO)

    const int t = threadIdx.x;
    const int bg = blockIdx.x;
    const int f0 = blockIdx.y * CH;

    for (int i = t; i < BPG * NSIG * CH; i += GCC_BLOCK) {
        int g = i / (NSIG * CH);
        int r = i - g * (NSIG * CH);
        int sig = r / CH, hl = r - sig * CH;
        int f = f0 + hl;
        const float2* sp = g_spec + ((size_t)(bg * BPG + g) * NSIG + sig) * NFREQ;
        int di = (g * NSIG + sig) * CHP + hl;
        suA[di] = (f <= 1024) ? sp[f] : make_float2(0.f, 0.f);
        suB[di] = (f <= 1023) ? sp[2048 - f] : make_float2(0.f, 0.f);
    }
    for (int i = t; i < CH * NTP; i += GCC_BLOCK) {
        int hl = i / NTP;
        int f = f0 + hl;
        T[i] = (f <= 1024) ? g_lagp[f * NTP + (i - hl * NTP)]
                           : make_float4(0.f, 0.f, 0.f, 0.f);
    }
    __syncthreads();

    const int g = t / 80, u = t - g * 80;
    if (u >= NPAIR) return;

    int n = 0, rem = u;
    #pragma unroll
    for (int k = 0; k < NSIG; k++) {
        int cnt = NSIG - k;
        if (rem < cnt) { n = k; break; }
        rem -= cnt;
    }
    const int m = n + rem;

    const float2* bA = suA + g * (NSIG * CHP);
    const float2* bB = suB + g * (NSIG * CHP);
    const float2* pAn = bA + n * CHP;
    const float2* pAm = bA + m * CHP;
    const float2* pBn = bB + n * CHP;
    const float2* pBm = bB + m * CHP;

    unsigned long long accU[NTP], accV[NTP];   // lanes = (even tau, odd tau)
    #pragma unroll
    for (int i = 0; i < NTP; i++) { accU[i] = 0ull; accV[i] = 0ull; }

    for (int hl = 0; hl < CH; hl++) {
        float2 a1 = pAn[hl], b1 = pAm[hl];
        float2 a2 = pBn[hl], b2 = pBm[hl];
        float U1 = a1.x * b1.x + a1.y * b1.y;
        float V1 = a1.y * b1.x - a1.x * b1.y;
        float U2 = a2.x * b2.x + a2.y * b2.y;
        float V2 = a2.y * b2.x - a2.x * b2.y;
        unsigned long long pU = pack2(U1 + U2, U1 - U2);   // (Ue, Uo)
        unsigned long long pV = pack2(V1 - V2, V1 + V2);   // (Vme, Vpo)
        const longlong2* tw = (const longlong2*)(T + (size_t)hl * NTP);
        #pragma unroll
        for (int tp = 0; tp < NTP; tp++) {
            longlong2 w = tw[tp];   // .x = (wcE,wcO), .y = (wsE,wsO)
            accU[tp] = fma_x2((unsigned long long)w.x, pU, accU[tp]);
            accV[tp] = fma_x2((unsigned long long)w.y, pV, accV[tp]);
        }
    }

    unsigned long long* pr = &g_part2[blockIdx.y][bg * BPG + g][u][0];
    #pragma unroll
    for (int tp = 0; tp < NTP; tp++) {
        float aE, aO, bE, bO;
        unpack2(accU[tp], aE, aO);
        unpack2(accV[tp], bE, bO);
        pr[2 * tp]     = pack2(aE - bE, aE + bE);   // (g+, g-) even tau
        pr[2 * tp + 1] = pack2(aO - bO, aO + bO);   // (g+, g-) odd tau
    }
}

// ================= reduce partials + triangular mirror expansion =================
__global__ void reduce_kernel(float* __restrict__ out) {
    int i = blockIdx.x * blockDim.x + threadIdx.x;
    if (i >= NBATCH * NPAIR * 13) return;
    int b = i / (NPAIR * 13);
    int r = i - b * (NPAIR * 13);
    int p = r / 13, k2 = r - p * 13;
    int tau0 = 2 * k2, tau1 = tau0 + 1;

    float gp0 = 0.f, gm0 = 0.f, gp1 = 0.f, gm1 = 0.f;
    #pragma unroll
    for (int s = 0; s < NS; s++) {
        ulonglong2 v = *(const ulonglong2*)&g_part2[s][b][p][tau0];
        float lo, hi;
        unpack2(v.x, lo, hi); gp0 += lo; gm0 += hi;
        unpack2(v.y, lo, hi); gp1 += lo; gm1 += hi;
    }

    int n = 0, rem = p;
    #pragma unroll
    for (int k = 0; k < NSIG; k++) {
        int cnt = NSIG - k;
        if (rem < cnt) { n = k; break; }
        rem -= cnt;
    }
    int m = n + rem;

    float* ob  = out + (size_t)b * OUTB;
    float* onm = ob + (n * NSIG + m) * NLAG;
    onm[tau0] = gp0;
    onm[tau1] = gp1;
    if (tau0 > 0) onm[NLAG - tau0] = gm0;
    onm[NLAG - tau1] = gm1;
    if (n != m) {
        float* omn = ob + (m * NSIG + n) * NLAG;
        omn[tau0] = gm0;
        omn[tau1] = gm1;
        if (tau0 > 0) omn[NLAG - tau0] = gp0;
        omn[NLAG - tau1] = gp1;
    }
}

// ================= launch =================
extern "C" void kernel_launch(void* const* d_in, const int* in_sizes, int n_in,
                              void* d_out, int out_size) {
    const float* x = (const float*)d_in[0];
    float* out = (float*)d_out;

    const int fft_smem = 32 * 64 * (int)sizeof(float2)
                       + 2 * 64 * 65 * (int)sizeof(float)
                       + 36 * 64 * (int)sizeof(float2);     // 68,096 B
    const int gcc_smem = 2 * BPG * NSIG * CHP * (int)sizeof(float2)
                       + CH * NTP * (int)sizeof(float4);    // 112,032 B

    cudaFuncSetAttribute(fft_phat_kernel, cudaFuncAttributeMaxDynamicSharedMemorySize, fft_smem);
    cudaFuncSetAttribute(gcc_kernel,      cudaFuncAttributeMaxDynamicSharedMemorySize, gcc_smem);

    init_tables_kernel<<<128, 256>>>();
    fft_phat_kernel<<<NBATCH * NSIG, 256, fft_smem>>>(x);
    gcc_kernel<<<dim3(NBATCH / BPG, NS), GCC_BLOCK, gcc_smem>>>();
    const int rthreads = NBATCH * NPAIR * 13;
    reduce_kernel<<<(rthreads + 255) / 256, 256>>>(out);
}

// round 9
// speedup vs baseline: 1.4264x; 1.0263x over previous
#include <cuda_runtime.h>
#include <math.h>

#define KLEN   4096
#define NFREQ  2049      // K/2 + 1
#define NH     1025      // folded freqs h=0..1024 (f=h pairs with f=2048-h)
#define NSIG   12
#define NBATCH 64
#define NLAG   51        // 2*25 + 1
#define NTAU   26        // tau = 0..25
#define NTP    13        // tau pairs (even, odd)
#define NPAIR  78        // 12*13/2 unique (n<=m) pairs
#define NPP    80        // padded pair dim for g_part3
#define NS     9         // frequency slices (144 CTAs)
#define CH     114       // folded freqs per slice (9*114 = 1026 >= 1025)
#define CHP    115       // padded smem stride (bank-conflict-free su loads)
#define BPG    4         // batches per gcc CTA
#define GCC_BLOCK 320    // 4 batch-groups x 80 threads (78 active pairs each)
#define OUTB   (NSIG*NSIG*NLAG)   // 7344 floats per batch

// -------- device scratch (static: no allocations allowed) --------
__device__ float2 g_dft2[36 * 64];                // (c,s) of 2*pi*j*a/64, rows j=0..35
__device__ float4 g_tw1[33 * 64];                 // [d][b]: (c, s, tmr, tms) stage-1 twiddle
__device__ float4 g_lagp[NH * NTP];               // (wcE, wcO, wsE, wsO) at [h*13+tp]
__device__ float2 g_spec[NBATCH * NSIG * NFREQ];  // PHAT-normalized spectra
__device__ unsigned long long g_part3[NS][NBATCH][NTAU][NPP];    // packed (g+, g-)

// -------- packed fp32x2 helpers --------
__device__ __forceinline__ unsigned long long fma_x2(unsigned long long a,
                                                     unsigned long long b,
                                                     unsigned long long c) {
    unsigned long long d;
    asm("fma.rn.f32x2 %0, %1, %2, %3;" : "=l"(d) : "l"(a), "l"(b), "l"(c));
    return d;
}
__device__ __forceinline__ unsigned long long pack2(float lo, float hi) {
    unsigned long long d;
    asm("mov.b64 %0, {%1, %2};" : "=l"(d) : "f"(lo), "f"(hi));
    return d;
}
__device__ __forceinline__ void unpack2(unsigned long long v, float& lo, float& hi) {
    asm("mov.b64 {%0, %1}, %2;" : "=f"(lo), "=f"(hi) : "l"(v));
}

// ================= init: twiddle tables =================
__global__ void init_tables_kernel() {
    int t = blockIdx.x * blockDim.x + threadIdx.x;
    int stride = gridDim.x * blockDim.x;
    for (int i = t; i < 36 * 64; i += stride) {
        int j = i >> 6, a = i & 63;
        float s, c;
        sincospif((float)(j * a) * (1.0f / 32.0f), &s, &c);   // 2*pi*j*a/64
        g_dft2[i] = make_float2(c, s);
    }
    for (int i = t; i < 33 * 64; i += stride) {
        int d = i >> 6, b = i & 63;
        float s, c, es, ec;
        sincospif((float)(b * d) * (1.0f / 2048.0f), &s, &c);   // W4096^{bd} = c - i s
        sincospif((float)b * (1.0f / 32.0f), &es, &ec);          // 2*pi*b/64
        float tmr = ec * c + es * s;     // cos(2pi b/64 - th)  (same exprs as old kernel)
        float tms = es * c - ec * s;     // sin(2pi b/64 - th)
        g_tw1[i] = make_float4(c, s, tmr, tms);
    }
    for (int i = t; i < NH * NTP; i += stride) {
        int h = i / NTP, tp = i - h * NTP;
        int tau0 = 2 * tp, tau1 = tau0 + 1;
        float s0, c0, s1, c1;
        sincospif((float)(h * tau0) * (1.0f / 2048.0f), &s0, &c0);
        sincospif((float)(h * tau1) * (1.0f / 2048.0f), &s1, &c1);
        float w = ((h == 0) ? 1.0f : 2.0f) * (1.0f / (float)KLEN);
        g_lagp[i] = make_float4(w * c0, w * c1, w * s0, w * s1);
    }
}

// ================= FFT (64x64 four-step, fully folded) + PHAT ========================
// Changes vs 79.9us baseline: stage-1 epilogue twiddle+mirror from g_tw1 table (replaces
// 9x sincospif + derive, ~-350 FMA/thread); PHAT uses rsqrtf (~-140 FMA/thread).
__global__ __launch_bounds__(256) void fft_phat_kernel(const float* __restrict__ x) {
    extern __shared__ float smem[];
    float2* xf  = (float2*)smem;            // [32][64]: (xe,xo); a=0 -> (x0,x32)
    float*  Yr  = (float*)(xf + 32 * 64);   // [64 b][65] (col d), odd stride
    float*  Yi  = Yr + 64 * 65;
    float2* dft = (float2*)(Yi + 64 * 65);  // rows j=0..32 valid; padded to 36 rows

    const int t = threadIdx.x;
    const float* xin = x + (size_t)blockIdx.x * KLEN;

    for (int i = t; i < 36 * 64; i += 256) dft[i] = g_dft2[i];
    for (int i = t; i < 32 * 64; i += 256) {
        int a = i >> 6, b = i & 63;
        if (a == 0) {
            xf[b] = make_float2(xin[b], xin[32 * 64 + b]);
        } else {
            float v1 = xin[a * 64 + b];
            float v2 = xin[(64 - a) * 64 + b];
            xf[a * 64 + b] = make_float2(v1 + v2, v1 - v2);
        }
    }
    __syncthreads();

    const int bb = t & 63, q0 = t >> 6;

    // ---- stage 1: 9 packed accumulators (yr, yi) for d = q0 + 4i ----
    {
        unsigned long long acc[9];
        #pragma unroll
        for (int i = 0; i < 9; i++) acc[i] = 0ull;

        // a = 1 (scalar head, keeps pair loads 16B-aligned)
        {
            float2 v = xf[64 + bb];
            unsigned long long vp = pack2(v.x, -v.y);
            #pragma unroll
            for (int i = 0; i < 9; i++) {
                int d = q0 + 4 * i;
                unsigned long long cs = *(const unsigned long long*)(dft + d * 64 + 1);
                acc[i] = fma_x2(vp, cs, acc[i]);
            }
        }
        // a = 2..31 in pairs: one 16B broadcast load gives both packed (c,s)
        for (int a = 2; a < 32; a += 2) {
            float2 v0 = xf[a * 64 + bb];
            float2 v1 = xf[(a + 1) * 64 + bb];
            unsigned long long vp0 = pack2(v0.x, -v0.y);
            unsigned long long vp1 = pack2(v1.x, -v1.y);
            #pragma unroll
            for (int i = 0; i < 9; i++) {
                int d = q0 + 4 * i;                    // d<=35; padded rows, junk discarded
                longlong2 w = *(const longlong2*)(dft + d * 64 + a);
                acc[i] = fma_x2(vp0, (unsigned long long)w.x, acc[i]);
                acc[i] = fma_x2(vp1, (unsigned long long)w.y, acc[i]);
            }
        }

        float2 x03 = xf[bb];           // (x0, x32)
        #pragma unroll
        for (int i = 0; i < 9; i++) {
            int d = q0 + 4 * i;
            if (d <= 32) {
                float yr, yi;
                unpack2(acc[i], yr, yi);
                yr += x03.x + ((d & 1) ? -x03.y : x03.y);
                float4 w = g_tw1[d * 64 + bb];          // (c, s, tmr, tms)
                Yr[bb * 65 + d] = yr * w.x + yi * w.y;
                Yi[bb * 65 + d] = yi * w.x - yr * w.y;
                if (d >= 1 && d <= 31) {
                    Yr[bb * 65 + (64 - d)] = yr * w.z - yi * w.w;
                    Yi[bb * 65 + (64 - d)] = -(yr * w.w + yi * w.z);
                }
            }
        }
    }
    __syncthreads();

    // ---- stage 2: d = bb, cc = q0 + 4j; b-folded, x2-unrolled with 16B twiddles ----
    {
        const int d = bb;
        float Xr[9], Xi[9];
        float z0r = Yr[d],           z0i = Yi[d];
        float z32r = Yr[32 * 65 + d], z32i = Yi[32 * 65 + d];
        #pragma unroll
        for (int j = 0; j < 9; j++) {
            int cc = q0 + 4 * j;
            float sg = (cc & 1) ? -1.f : 1.f;
            Xr[j] = z0r + sg * z32r;
            Xi[j] = z0i + sg * z32i;
        }

        // b = 1 (scalar head)
        {
            float z1r = Yr[65 + d],        z1i = Yi[65 + d];
            float z2r = Yr[63 * 65 + d],   z2i = Yi[63 * 65 + d];
            float zex = z1r + z2r, zey = z1i + z2i;
            float zox = z1r - z2r, zoy = z1i - z2i;
            #pragma unroll
            for (int j = 0; j < 9; j++) {
                int cc = q0 + 4 * j;
                float2 cs = dft[cc * 64 + 1];
                Xr[j] += zex * cs.x + zoy * cs.y;
                Xi[j] += zey * cs.x - zox * cs.y;
            }
        }
        // b = 2..31 in pairs
        for (int b = 2; b < 32; b += 2) {
            float z1r0 = Yr[b * 65 + d],          z1i0 = Yi[b * 65 + d];
            float z2r0 = Yr[(64 - b) * 65 + d],   z2i0 = Yi[(64 - b) * 65 + d];
            float z1r1 = Yr[(b + 1) * 65 + d],    z1i1 = Yi[(b + 1) * 65 + d];
            float z2r1 = Yr[(63 - b) * 65 + d],   z2i1 = Yi[(63 - b) * 65 + d];
            float zex0 = z1r0 + z2r0, zey0 = z1i0 + z2i0;
            float zox0 = z1r0 - z2r0, zoy0 = z1i0 - z2i0;
            float zex1 = z1r1 + z2r1, zey1 = z1i1 + z2i1;
            float zox1 = z1r1 - z2r1, zoy1 = z1i1 - z2i1;
            #pragma unroll
            for (int j = 0; j < 9; j++) {
                int cc = q0 + 4 * j;                   // <=35; padded rows, junk discarded
                float4 cs = *(const float4*)(dft + cc * 64 + b);
                Xr[j] += zex0 * cs.x + zoy0 * cs.y;
                Xi[j] += zey0 * cs.x - zox0 * cs.y;
                Xr[j] += zex1 * cs.z + zoy1 * cs.w;
                Xi[j] += zey1 * cs.z - zox1 * cs.w;
            }
        }

        float2* outp = g_spec + (size_t)blockIdx.x * NFREQ;
        #pragma unroll
        for (int j = 0; j < 9; j++) {
            int cc = q0 + 4 * j;
            int f = cc * 64 + d;
            if (cc <= 32 && f <= 2048) {
                float u = fmaf(Xr[j], Xr[j], fmaf(Xi[j], Xi[j], 1e-30f));
                float inv = rsqrtf(u);                  // ~2ulp; eps folded into u
                outp[f] = make_float2(Xr[j] * inv, Xi[j] * inv);
            }
        }
    }
}

// ================= GCC: folded cross-spectrum x lag twiddles =========================
// Unchanged mainloop; epilogue writes to pair-major g_part3 (coalesced 640B runs).
__global__ __launch_bounds__(GCC_BLOCK, 2) void gcc_kernel() {
    extern __shared__ float smem[];
    float2* suA = (float2*)smem;                      // [BPG][12][CHP] spectra at f
    float2* suB = suA + BPG * NSIG * CHP;             // [BPG][12][CHP] spectra at 2048-f
    float4* T   = (float4*)(suB + BPG * NSIG * CHP);  // [CH][13] (wcE,wcO,wsE,wsO)

    const int t = threadIdx.x;
    const int bg = blockIdx.x;
    const int f0 = blockIdx.y * CH;

    for (int i = t; i < BPG * NSIG * CH; i += GCC_BLOCK) {
        int g = i / (NSIG * CH);
        int r = i - g * (NSIG * CH);
        int sig = r / CH, hl = r - sig * CH;
        int f = f0 + hl;
        const float2* sp = g_spec + ((size_t)(bg * BPG + g) * NSIG + sig) * NFREQ;
        int di = (g * NSIG + sig) * CHP + hl;
        suA[di] = (f <= 1024) ? sp[f] : make_float2(0.f, 0.f);
        suB[di] = (f <= 1023) ? sp[2048 - f] : make_float2(0.f, 0.f);
    }
    for (int i = t; i < CH * NTP; i += GCC_BLOCK) {
        int hl = i / NTP;
        int f = f0 + hl;
        T[i] = (f <= 1024) ? g_lagp[f * NTP + (i - hl * NTP)]
                           : make_float4(0.f, 0.f, 0.f, 0.f);
    }
    __syncthreads();

    const int g = t / 80, u = t - g * 80;
    if (u >= NPAIR) return;

    int n = 0, rem = u;
    #pragma unroll
    for (int k = 0; k < NSIG; k++) {
        int cnt = NSIG - k;
        if (rem < cnt) { n = k; break; }
        rem -= cnt;
    }
    const int m = n + rem;

    const float2* bA = suA + g * (NSIG * CHP);
    const float2* bB = suB + g * (NSIG * CHP);
    const float2* pAn = bA + n * CHP;
    const float2* pAm = bA + m * CHP;
    const float2* pBn = bB + n * CHP;
    const float2* pBm = bB + m * CHP;

    unsigned long long accU[NTP], accV[NTP];   // lanes = (even tau, odd tau)
    #pragma unroll
    for (int i = 0; i < NTP; i++) { accU[i] = 0ull; accV[i] = 0ull; }

    for (int hl = 0; hl < CH; hl++) {
        float2 a1 = pAn[hl], b1 = pAm[hl];
        float2 a2 = pBn[hl], b2 = pBm[hl];
        float U1 = a1.x * b1.x + a1.y * b1.y;
        float V1 = a1.y * b1.x - a1.x * b1.y;
        float U2 = a2.x * b2.x + a2.y * b2.y;
        float V2 = a2.y * b2.x - a2.x * b2.y;
        unsigned long long pU = pack2(U1 + U2, U1 - U2);   // (Ue, Uo)
        unsigned long long pV = pack2(V1 - V2, V1 + V2);   // (Vme, Vpo)
        const longlong2* tw = (const longlong2*)(T + (size_t)hl * NTP);
        #pragma unroll
        for (int tp = 0; tp < NTP; tp++) {
            longlong2 w = tw[tp];   // .x = (wcE,wcO), .y = (wsE,wsO)
            accU[tp] = fma_x2((unsigned long long)w.x, pU, accU[tp]);
            accV[tp] = fma_x2((unsigned long long)w.y, pV, accV[tp]);
        }
    }

    const int batch = bg * BPG + g;
    #pragma unroll
    for (int tp = 0; tp < NTP; tp++) {
        float aE, aO, bE, bO;
        unpack2(accU[tp], aE, aO);
        unpack2(accV[tp], bE, bO);
        g_part3[blockIdx.y][batch][2 * tp][u]     = pack2(aE - bE, aE + bE);
        g_part3[blockIdx.y][batch][2 * tp + 1][u] = pack2(aO - bO, aO + bO);
    }
}

// ================= reduce partials + triangular mirror expansion =================
// thread = (batch, tau-pair, pair) -> lanes span consecutive pairs (coalesced reads).
__global__ void reduce_kernel(float* __restrict__ out) {
    int i = blockIdx.x * blockDim.x + threadIdx.x;
    if (i >= NBATCH * 13 * NPAIR) return;
    int b = i / (13 * NPAIR);
    int r = i - b * (13 * NPAIR);
    int k2 = r / NPAIR, p = r - k2 * NPAIR;
    int tau0 = 2 * k2, tau1 = tau0 + 1;

    float gp0 = 0.f, gm0 = 0.f, gp1 = 0.f, gm1 = 0.f;
    #pragma unroll
    for (int s = 0; s < NS; s++) {
        float lo, hi;
        unpack2(g_part3[s][b][tau0][p], lo, hi); gp0 += lo; gm0 += hi;
        unpack2(g_part3[s][b][tau1][p], lo, hi); gp1 += lo; gm1 += hi;
    }

    int n = 0, rem = p;
    #pragma unroll
    for (int k = 0; k < NSIG; k++) {
        int cnt = NSIG - k;
        if (rem < cnt) { n = k; break; }
        rem -= cnt;
    }
    int m = n + rem;

    float* ob  = out + (size_t)b * OUTB;
    float* onm = ob + (n * NSIG + m) * NLAG;
    onm[tau0] = gp0;
    onm[tau1] = gp1;
    if (tau0 > 0) onm[NLAG - tau0] = gm0;
    onm[NLAG - tau1] = gm1;
    if (n != m) {
        float* omn = ob + (m * NSIG + n) * NLAG;
        omn[tau0] = gm0;
        omn[tau1] = gm1;
        if (tau0 > 0) omn[NLAG - tau0] = gp0;
        omn[NLAG - tau1] = gp1;
    }
}

// ================= launch =================
extern "C" void kernel_launch(void* const* d_in, const int* in_sizes, int n_in,
                              void* d_out, int out_size) {
    const float* x = (const float*)d_in[0];
    float* out = (float*)d_out;

    const int fft_smem = 32 * 64 * (int)sizeof(float2)
                       + 2 * 64 * 65 * (int)sizeof(float)
                       + 36 * 64 * (int)sizeof(float2);     // 68,096 B
    const int gcc_smem = 2 * BPG * NSIG * CHP * (int)sizeof(float2)
                       + CH * NTP * (int)sizeof(float4);    // 112,032 B

    cudaFuncSetAttribute(fft_phat_kernel, cudaFuncAttributeMaxDynamicSharedMemorySize, fft_smem);
    cudaFuncSetAttribute(gcc_kernel,      cudaFuncAttributeMaxDynamicSharedMemorySize, gcc_smem);

    init_tables_kernel<<<128, 256>>>();
    fft_phat_kernel<<<NBATCH * NSIG, 256, fft_smem>>>(x);
    gcc_kernel<<<dim3(NBATCH / BPG, NS), GCC_BLOCK, gcc_smem>>>();
    const int rthreads = NBATCH * 13 * NPAIR;
    reduce_kernel<<<(rthreads + 255) / 256, 256>>>(out);
}